// round 14
// baseline (speedup 1.0000x reference)
#include <cuda_runtime.h>
#include <math.h>
#include <stdint.h>

#define B_  4
#define S_  2048
#define H_  1024
#define NH_ 16
#define HD_ 64
#define M_  (B_ * S_)
#define SCALE_INV 0.125f

// Scratch (device globals — no allocation allowed)
__device__ float g_Q[M_ * H_];            // [B,NH,S,HD] tf32, x1/8, k-PERMUTED
__device__ float g_K[M_ * H_];            // [B,NH,S,HD] tf32, k-PERMUTED
__device__ float g_V[M_ * H_];            // [B,NH,S,HD] tf32 (unpermuted)
__device__ float g_X[M_ * H_];            // [B,S,H]     tf32 (unpermuted)
__device__ float g_psum[64 * S_ * 32];    // [bh][q][kblock(64)] partial row sums
__device__ float g_rW[4][H_ * H_];        // tf32 Wq,Wk,Wv,Wo, k-PERMUTED

// Permutation within each 8-col group: pos(c) = (c&3)*2 + ((c>>2)&1).
// Stored this way, the MMA fragment pair (k, k+4) is ADJACENT -> LDS.64.

// ---------------------------------------------------------------------------
__device__ __forceinline__ uint32_t f2tf32(float x) {  // round-to-nearest tf32
    uint32_t r; asm("cvt.rna.tf32.f32 %0, %1;" : "=r"(r) : "f"(x)); return r;
}
__device__ __forceinline__ float tf32f(float x) { return __uint_as_float(f2tf32(x)); }
__device__ __forceinline__ int kperm(int c) {   // column -> permuted position
    return (c & ~7) | ((c & 3) * 2 + ((c >> 2) & 1));
}

__device__ __forceinline__ void mma_tf32(float* c, const uint32_t* a, const uint32_t* b) {
    asm volatile("mma.sync.aligned.m16n8k8.row.col.f32.tf32.tf32.f32 "
        "{%0,%1,%2,%3}, {%4,%5,%6,%7}, {%8,%9}, {%0,%1,%2,%3};"
        : "+f"(c[0]), "+f"(c[1]), "+f"(c[2]), "+f"(c[3])
        : "r"(a[0]), "r"(a[1]), "r"(a[2]), "r"(a[3]), "r"(b[0]), "r"(b[1]));
}

// Standard A fragment from unpermuted SMEM: 4x LDS.32
__device__ __forceinline__ void lda_frag(uint32_t* a, const float* s, int lds,
                                         int mbase, int k, int lane) {
    const float* p = s + (size_t)(mbase + (lane >> 2)) * lds + k + (lane & 3);
    a[0] = __float_as_uint(p[0]);
    a[1] = __float_as_uint(p[8 * lds]);
    a[2] = __float_as_uint(p[4]);
    a[3] = __float_as_uint(p[8 * lds + 4]);
}
// A fragment from k-PERMUTED SMEM: 2x LDS.64
__device__ __forceinline__ void lda_frag_perm(uint32_t* a, const float* s, int lds,
                                              int mbase, int ks, int lane) {
    const float* p = s + (size_t)(mbase + (lane >> 2)) * lds + ks * 8 + (lane & 3) * 2;
    float2 v0 = *(const float2*)p;
    float2 v1 = *(const float2*)(p + 8 * lds);
    a[0] = __float_as_uint(v0.x);
    a[2] = __float_as_uint(v0.y);
    a[1] = __float_as_uint(v1.x);
    a[3] = __float_as_uint(v1.y);
}
// Standard B fragment: 2x LDS.32
__device__ __forceinline__ void ldb_frag(uint32_t* b, const float* s, int lds,
                                         int nbase, int k, int lane) {
    const float* p = s + (size_t)(nbase + (lane >> 2)) * lds + k + (lane & 3);
    b[0] = __float_as_uint(p[0]);
    b[1] = __float_as_uint(p[4]);
}
// B fragment from k-PERMUTED SMEM: 1x LDS.64
__device__ __forceinline__ void ldb_frag_perm(uint32_t* b, const float* s, int lds,
                                              int nbase, int ks, int lane) {
    float2 v = *(const float2*)(s + (size_t)(nbase + (lane >> 2)) * lds
                                + ks * 8 + (lane & 3) * 2);
    b[0] = __float_as_uint(v.x);
    b[1] = __float_as_uint(v.y);
}

__device__ __forceinline__ uint32_t smaddr(const void* p) {
    return (uint32_t)__cvta_generic_to_shared(p);
}
#define CP_ASYNC16(dst, src) \
    asm volatile("cp.async.cg.shared.global [%0], [%1], 16;" :: "r"(dst), "l"(src))
#define CP_COMMIT() asm volatile("cp.async.commit_group;" ::: "memory")
#define CP_WAIT0()  asm volatile("cp.async.wait_group 0;" ::: "memory")
#define CP_WAIT1()  asm volatile("cp.async.wait_group 1;" ::: "memory")

// ---------------------------------------------------------------------------
// Weight pre-round + k-permute: g_rW[y][n][kperm(k)] = tf32(W_y[n][k]).
// ---------------------------------------------------------------------------
__global__ __launch_bounds__(256) void round_w(const float* __restrict__ Wq,
                                               const float* __restrict__ Wk,
                                               const float* __restrict__ Wv,
                                               const float* __restrict__ Wo,
                                               float* __restrict__ out) {
    const int which = blockIdx.y;
    const float* src = (which == 0) ? Wq : (which == 1) ? Wk : (which == 2) ? Wv : Wo;
    float* dst = out + (size_t)which * H_ * H_;
    int i = blockIdx.x * 256 + threadIdx.x;   // n4 = H*H/4
    float4 v = ((const float4*)src)[i];
    int base = i * 4;                          // column of v.x (row-major flat)
    int rowoff = base & ~1023;                 // start of this W row (H_=1024)
    int c = base & 1023;
    dst[rowoff + kperm(c)]     = tf32f(v.x);
    dst[rowoff + kperm(c + 1)] = tf32f(v.y);
    dst[rowoff + kperm(c + 2)] = tf32f(v.z);
    dst[rowoff + kperm(c + 3)] = tf32f(v.w);
}

// ---------------------------------------------------------------------------
// Projection GEMM: C[m,n] = A[m,:]·W[n,:] + bias[n]. Tile 128x128.
// A: raw fp32, register-prefetched, tf32-rounded at STS (unpermuted).
// W: pre-rounded + k-PERMUTED -> B fragments are 1x LDS.64.
// mode 0: out[m][n] fp32
// mode 1: out[b,h,s,d] tf32 (V — unpermuted)
// mode 2: out[b,h,s,kperm(d)] tf32 * 1/8 (Q — permuted + scaled)
// mode 3: out[b,h,s,kperm(d)] tf32 (K — permuted)
// ---------------------------------------------------------------------------
__global__ __launch_bounds__(256, 2) void proj_mma(const float* __restrict__ A,
                                                   const float* __restrict__ W,
                                                   const float* __restrict__ bias,
                                                   float* __restrict__ out, int mode) {
    __shared__ __align__(16) float sA[2][128][36];
    __shared__ __align__(16) float sB[2][128][36];
    const int tid = threadIdx.x, lane = tid & 31, w = tid >> 5;
    const int wm = (w >> 2) * 64, wn = (w & 3) * 32;
    const int m0 = blockIdx.y * 128, n0 = blockIdx.x * 128;

    float acc[4][4][4] = {};
    float4 aReg[4];

    int rr[4], cc[4];
    #pragma unroll
    for (int i = 0; i < 4; i++) {
        int idx = tid + i * 256;
        rr[i] = idx >> 3;
        cc[i] = (idx & 7) * 4;
    }

    #pragma unroll
    for (int i = 0; i < 4; i++)
        aReg[i] = *(const float4*)&A[(size_t)(m0 + rr[i]) * H_ + cc[i]];
    #pragma unroll
    for (int i = 0; i < 4; i++)
        CP_ASYNC16(smaddr(&sB[0][rr[i]][cc[i]]), &W[(size_t)(n0 + rr[i]) * H_ + cc[i]]);
    CP_COMMIT();

    for (int it = 0; it < 32; it++) {
        const int s = it & 1;

        #pragma unroll
        for (int i = 0; i < 4; i++) {
            float4 v = aReg[i];
            v.x = tf32f(v.x); v.y = tf32f(v.y); v.z = tf32f(v.z); v.w = tf32f(v.w);
            *(float4*)&sA[s][rr[i]][cc[i]] = v;
        }

        if (it + 1 < 32) {
            const int kn = (it + 1) * 32, sn = s ^ 1;
            #pragma unroll
            for (int i = 0; i < 4; i++)
                aReg[i] = *(const float4*)&A[(size_t)(m0 + rr[i]) * H_ + kn + cc[i]];
            #pragma unroll
            for (int i = 0; i < 4; i++)
                CP_ASYNC16(smaddr(&sB[sn][rr[i]][cc[i]]), &W[(size_t)(n0 + rr[i]) * H_ + kn + cc[i]]);
            CP_COMMIT();
            CP_WAIT1();
        } else {
            CP_WAIT0();
        }
        __syncthreads();

        #pragma unroll
        for (int ks = 0; ks < 4; ks++) {
            uint32_t af[4][4], bf[4][2];
            #pragma unroll
            for (int mt = 0; mt < 4; mt++)
                lda_frag(af[mt], &sA[s][0][0], 36, wm + mt * 16, ks * 8, lane);
            #pragma unroll
            for (int nt = 0; nt < 4; nt++)
                ldb_frag_perm(bf[nt], &sB[s][0][0], 36, wn + nt * 8, ks, lane);
            #pragma unroll
            for (int mt = 0; mt < 4; mt++)
                #pragma unroll
                for (int nt = 0; nt < 4; nt++)
                    mma_tf32(acc[mt][nt], af[mt], bf[nt]);
        }
        __syncthreads();   // REQUIRED: protect sA[s]/sB[s] from next iter's writes
    }

    #pragma unroll
    for (int mt = 0; mt < 4; mt++) {
        #pragma unroll
        for (int nt = 0; nt < 4; nt++) {
            int r0 = m0 + wm + mt * 16 + (lane >> 2);
            int c0 = n0 + wn + nt * 8 + (lane & 3) * 2;
            #pragma unroll
            for (int e = 0; e < 4; e++) {
                int m = r0 + (e >> 1) * 8;
                int n = c0 + (e & 1);
                float v = acc[mt][nt][e] + bias[n];
                if (mode == 0) {
                    out[(size_t)m * H_ + n] = v;
                } else {
                    int b = m >> 11, sq = m & 2047, h = n >> 6, dd = n & 63;
                    float o = tf32f(v);
                    if (mode == 2) o *= SCALE_INV;               // exact
                    if (mode >= 2) dd = kperm(dd);               // Q/K permuted
                    out[(((size_t)(b * NH_ + h) * S_) + sq) * HD_ + dd] = o;
                }
            }
        }
    }
}

// ---------------------------------------------------------------------------
// Energy + exp + mask (R7 shape). Tile 128(q) x 64(k). Q/K inputs k-PERMUTED
// -> all fragments are LDS.64 (mainloop LDS halved). Q pre-scaled by 1/8.
// Mask prefetched + bit-packed. Writes tf32 unnormalized P + psum.
// ---------------------------------------------------------------------------
__global__ __launch_bounds__(256, 3) void energy_exp(const int* __restrict__ mask,
                                                     float* __restrict__ attn,
                                                     float* __restrict__ psum) {
    __shared__ __align__(16) union {
        struct { float A[128][68]; float B[64][68]; } ld;
        float E[128][68];
    } sm;
    const int tid = threadIdx.x, lane = tid & 31, w = tid >> 5;
    const int wm = (w >> 1) * 32, wn = (w & 1) * 32;
    const int bh = blockIdx.z, b = bh >> 4;
    const int q0 = blockIdx.y * 128, k0 = blockIdx.x * 64;
    const int kblk = blockIdx.x;
    const float* Qb = g_Q + (size_t)bh * S_ * HD_;
    const float* Kb = g_K + (size_t)bh * S_ * HD_;

    #pragma unroll
    for (int i = tid; i < 2048; i += 256) {
        int r = i >> 4, c4 = (i & 15) * 4;
        CP_ASYNC16(smaddr(&sm.ld.A[r][c4]), &Qb[(size_t)(q0 + r) * HD_ + c4]);
    }
    #pragma unroll
    for (int i = tid; i < 1024; i += 256) {
        int r = i >> 4, c4 = (i & 15) * 4;
        CP_ASYNC16(smaddr(&sm.ld.B[r][c4]), &Kb[(size_t)(k0 + r) * HD_ + c4]);
    }
    CP_COMMIT();

    const int* mb = mask + (size_t)b * S_ * S_;
    const int cl = (tid & 15) * 4;
    const int k = k0 + cl;
    uint32_t pmask = 0;
    #pragma unroll
    for (int j = 0; j < 8; j++) {
        int q = q0 + j * 16 + (tid >> 4);
        int4 mv = *(const int4*)&mb[(size_t)q * S_ + k];
        uint32_t bits = (mv.x ? 1u : 0u) | (mv.y ? 2u : 0u)
                      | (mv.z ? 4u : 0u) | (mv.w ? 8u : 0u);
        pmask |= bits << (4 * j);
    }

    CP_WAIT0();
    __syncthreads();

    float acc[2][4][4] = {};
    #pragma unroll
    for (int ks = 0; ks < 8; ks++) {
        uint32_t af[2][4], bf[4][2];
        #pragma unroll
        for (int mt = 0; mt < 2; mt++)
            lda_frag_perm(af[mt], &sm.ld.A[0][0], 68, wm + mt * 16, ks, lane);
        #pragma unroll
        for (int nt = 0; nt < 4; nt++)
            ldb_frag_perm(bf[nt], &sm.ld.B[0][0], 68, wn + nt * 8, ks, lane);
        #pragma unroll
        for (int mt = 0; mt < 2; mt++)
            #pragma unroll
            for (int nt = 0; nt < 4; nt++)
                mma_tf32(acc[mt][nt], af[mt], bf[nt]);
    }
    __syncthreads();   // all warps done reading Q/K before E overwrites

    #pragma unroll
    for (int mt = 0; mt < 2; mt++) {
        int r = wm + mt * 16 + (lane >> 2);
        #pragma unroll
        for (int nt = 0; nt < 4; nt++) {
            int lc = wn + nt * 8 + (lane & 3) * 2;
            sm.E[r][lc]         = acc[mt][nt][0];
            sm.E[r][lc + 1]     = acc[mt][nt][1];
            sm.E[r + 8][lc]     = acc[mt][nt][2];
            sm.E[r + 8][lc + 1] = acc[mt][nt][3];
        }
    }
    __syncthreads();

    float* ab = attn + (size_t)bh * S_ * S_;
    #pragma unroll
    for (int j = 0; j < 8; j++) {
        int row = j * 16 + (tid >> 4);
        int q = q0 + row;
        float4 ev = *(float4*)&sm.E[row][cl];
        uint32_t bits = (pmask >> (4 * j)) & 0xfu;
        float p0 = (bits & 1u) ? tf32f(__expf(ev.x)) : 0.f;
        float p1 = (bits & 2u) ? tf32f(__expf(ev.y)) : 0.f;
        float p2 = (bits & 4u) ? tf32f(__expf(ev.z)) : 0.f;
        float p3 = (bits & 8u) ? tf32f(__expf(ev.w)) : 0.f;
        float4 pv4 = { p0, p1, p2, p3 };
        *(float4*)&ab[(size_t)q * S_ + k] = pv4;
        float v = (p0 + p1) + (p2 + p3);
        v += __shfl_xor_sync(0xffffffffu, v, 1);
        v += __shfl_xor_sync(0xffffffffu, v, 2);
        v += __shfl_xor_sync(0xffffffffu, v, 4);
        v += __shfl_xor_sync(0xffffffffu, v, 8);
        if ((tid & 15) == 0)
            psum[((size_t)bh * S_ + q) * 32 + kblk] = v;
    }
}

// ---------------------------------------------------------------------------
// PV + normalize (R10 version, unchanged). Tile 128(q) x 64(d).
// ---------------------------------------------------------------------------
__global__ __launch_bounds__(256, 3) void pv_norm(float* __restrict__ attn,
                                                  const float* __restrict__ psum) {
    __shared__ __align__(16) float sP[2][128][36];
    __shared__ __align__(16) float sV[2][32][68];
    __shared__ float sInv[128];
    const int tid = threadIdx.x, lane = tid & 31, w = tid >> 5;
    const int wm = (w >> 1) * 32, wn = (w & 1) * 32;
    const int bh = blockIdx.y, b = bh >> 4, h = bh & 15;
    const int q0 = blockIdx.x * 128;
    float* Pb = attn + (size_t)bh * S_ * S_;
    const float* Vb = g_V + (size_t)bh * S_ * HD_;

    if (tid < 128) {
        const float* ps = psum + ((size_t)bh * S_ + q0 + tid) * 32;
        float sum = 0.f;
        #pragma unroll
        for (int i = 0; i < 32; i++) sum += ps[i];
        sInv[tid] = 1.0f / sum;
    }

    #pragma unroll
    for (int i = tid; i < 1024; i += 256) {
        int r = i >> 3, c4 = (i & 7) * 4;
        CP_ASYNC16(smaddr(&sP[0][r][c4]), &Pb[(size_t)(q0 + r) * S_ + c4]);
    }
    #pragma unroll
    for (int i = tid; i < 512; i += 256) {
        int r = i >> 4, c4 = (i & 15) * 4;
        CP_ASYNC16(smaddr(&sV[0][r][c4]), &Vb[(size_t)r * HD_ + c4]);
    }
    CP_COMMIT();

    float acc[2][4][4] = {};

    for (int it = 0; it < 64; it++) {
        const int kc = it * 32, s = it & 1;
        if (it + 1 < 64) {
            const int kn = kc + 32, sn = s ^ 1;
            #pragma unroll
            for (int i = tid; i < 1024; i += 256) {
                int r = i >> 3, c4 = (i & 7) * 4;
                CP_ASYNC16(smaddr(&sP[sn][r][c4]), &Pb[(size_t)(q0 + r) * S_ + kn + c4]);
            }
            #pragma unroll
            for (int i = tid; i < 512; i += 256) {
                int r = i >> 4, c4 = (i & 15) * 4;
                CP_ASYNC16(smaddr(&sV[sn][r][c4]), &Vb[(size_t)(kn + r) * HD_ + c4]);
            }
            CP_COMMIT();
            CP_WAIT1();
        } else {
            CP_WAIT0();
        }
        __syncthreads();

        #pragma unroll
        for (int ks = 0; ks < 4; ks++) {
            uint32_t af[2][4], bf[4][2];
            #pragma unroll
            for (int mt = 0; mt < 2; mt++) lda_frag(af[mt], &sP[s][0][0], 36, wm + mt * 16, ks * 8, lane);
            #pragma unroll
            for (int nt = 0; nt < 4; nt++) {
                const float* p = &sV[s][ks * 8 + (lane & 3)][wn + nt * 8 + (lane >> 2)];
                bf[nt][0] = __float_as_uint(p[0]);
                bf[nt][1] = __float_as_uint(p[4 * 68]);
            }
            #pragma unroll
            for (int mt = 0; mt < 2; mt++)
                #pragma unroll
                for (int nt = 0; nt < 4; nt++)
                    mma_tf32(acc[mt][nt], af[mt], bf[nt]);
        }

        #pragma unroll
        for (int i = tid; i < 1024; i += 256) {
            int r = i >> 3, c4 = (i & 7) * 4;
            float inv = sInv[r];
            float4 v = *(float4*)&sP[s][r][c4];
            v.x *= inv; v.y *= inv; v.z *= inv; v.w *= inv;
            *(float4*)&Pb[(size_t)(q0 + r) * S_ + kc + c4] = v;
        }
        __syncthreads();
    }

    #pragma unroll
    for (int mt = 0; mt < 2; mt++) {
        #pragma unroll
        for (int nt = 0; nt < 4; nt++) {
            int rr = wm + mt * 16 + (lane >> 2);
            int c0 = wn + nt * 8 + (lane & 3) * 2;
            #pragma unroll
            for (int e = 0; e < 4; e++) {
                int rl = rr + (e >> 1) * 8;
                int q = q0 + rl;
                int d = c0 + (e & 1);
                g_X[((size_t)(b * S_ + q)) * H_ + h * HD_ + d] = tf32f(acc[mt][nt][e] * sInv[rl]);
            }
        }
    }
}

// ---------------------------------------------------------------------------
extern "C" void kernel_launch(void* const* d_in, const int* in_sizes, int n_in,
                              void* d_out, int out_size) {
    const float* query = (const float*)d_in[0];
    const float* key   = (const float*)d_in[1];
    const float* value = (const float*)d_in[2];
    const int*   mask  = (const int*)d_in[3];
    const float* Wq = (const float*)d_in[4];  const float* bq = (const float*)d_in[5];
    const float* Wk = (const float*)d_in[6];  const float* bk = (const float*)d_in[7];
    const float* Wv = (const float*)d_in[8];  const float* bv = (const float*)d_in[9];
    const float* Wo = (const float*)d_in[10]; const float* bo = (const float*)d_in[11];

    float* out  = (float*)d_out;
    float* attn = out + (size_t)B_ * S_ * H_;

    float *gQ, *gK, *gV, *gX, *gPS, *gW;
    cudaGetSymbolAddress((void**)&gQ, g_Q);
    cudaGetSymbolAddress((void**)&gK, g_K);
    cudaGetSymbolAddress((void**)&gV, g_V);
    cudaGetSymbolAddress((void**)&gX, g_X);
    cudaGetSymbolAddress((void**)&gPS, g_psum);
    cudaGetSymbolAddress((void**)&gW, g_rW);

    float* rWq = gW;
    float* rWk = gW + (size_t)H_ * H_;
    float* rWv = gW + (size_t)2 * H_ * H_;
    float* rWo = gW + (size_t)3 * H_ * H_;

    dim3 grid_rw(H_ * H_ / 4 / 256, 4);        // (1024, 4)
    round_w<<<grid_rw, 256>>>(Wq, Wk, Wv, Wo, gW);

    dim3 grid_proj(H_ / 128, M_ / 128);        // (8, 64)
    proj_mma<<<grid_proj, 256>>>(query, rWq, bq, gQ, 2);   // Q: perm + 1/8
    proj_mma<<<grid_proj, 256>>>(key,   rWk, bk, gK, 3);   // K: perm
    proj_mma<<<grid_proj, 256>>>(value, rWv, bv, gV, 1);   // V: unperm
    // g_X is consumed as A (unpermuted path) by the final projection.

    dim3 grid_e(S_ / 64, S_ / 128, B_ * NH_);  // (32, 16, 64)
    energy_exp<<<grid_e, 256>>>(mask, attn, gPS);

    dim3 grid_pv(S_ / 128, B_ * NH_);          // (16, 64)
    pv_norm<<<grid_pv, 256>>>(attn, gPS);

    proj_mma<<<grid_proj, 256>>>(gX, rWo, bo, out, 0);
}

// round 15
// speedup vs baseline: 1.1274x; 1.1274x over previous
#include <cuda_runtime.h>
#include <math.h>
#include <stdint.h>

#define B_  4
#define S_  2048
#define H_  1024
#define NH_ 16
#define HD_ 64
#define M_  (B_ * S_)
#define SCALE_INV 0.125f

// Scratch (device globals — no allocation allowed)
__device__ float g_Q[M_ * H_];            // [B,NH,S,HD]  tf32-rounded, pre-scaled by 1/8
__device__ float g_K[M_ * H_];            // [B,NH,S,HD]  tf32-rounded
__device__ float g_V[M_ * H_];            // [B,NH,S,HD]  tf32-rounded
__device__ float g_X[M_ * H_];            // [B,S,H]
__device__ float g_psum[64 * S_ * 32];    // [bh][q][kblock(64)] partial row sums

// ---------------------------------------------------------------------------
__device__ __forceinline__ uint32_t f2tf32(float x) {  // round-to-nearest tf32
    uint32_t r; asm("cvt.rna.tf32.f32 %0, %1;" : "=r"(r) : "f"(x)); return r;
}
__device__ __forceinline__ float tf32f(float x) { return __uint_as_float(f2tf32(x)); }

__device__ __forceinline__ void mma_tf32(float* c, const uint32_t* a, const uint32_t* b) {
    asm volatile("mma.sync.aligned.m16n8k8.row.col.f32.tf32.tf32.f32 "
        "{%0,%1,%2,%3}, {%4,%5,%6,%7}, {%8,%9}, {%0,%1,%2,%3};"
        : "+f"(c[0]), "+f"(c[1]), "+f"(c[2]), "+f"(c[3])
        : "r"(a[0]), "r"(a[1]), "r"(a[2]), "r"(a[3]), "r"(b[0]), "r"(b[1]));
}

__device__ __forceinline__ void lda_frag(uint32_t* a, const float* s, int lds,
                                         int mbase, int k, int lane) {
    const float* p = s + (size_t)(mbase + (lane >> 2)) * lds + k + (lane & 3);
    a[0] = __float_as_uint(p[0]);
    a[1] = __float_as_uint(p[8 * lds]);
    a[2] = __float_as_uint(p[4]);
    a[3] = __float_as_uint(p[8 * lds + 4]);
}
__device__ __forceinline__ void ldb_frag(uint32_t* b, const float* s, int lds,
                                         int nbase, int k, int lane) {
    const float* p = s + (size_t)(nbase + (lane >> 2)) * lds + k + (lane & 3);
    b[0] = __float_as_uint(p[0]);
    b[1] = __float_as_uint(p[4]);
}

__device__ __forceinline__ uint32_t smaddr(const void* p) {
    return (uint32_t)__cvta_generic_to_shared(p);
}
#define CP_ASYNC16(dst, src) \
    asm volatile("cp.async.cg.shared.global [%0], [%1], 16;" :: "r"(dst), "l"(src))
#define CP_COMMIT() asm volatile("cp.async.commit_group;" ::: "memory")
#define CP_WAIT0()  asm volatile("cp.async.wait_group 0;" ::: "memory")
#define CP_WAIT1()  asm volatile("cp.async.wait_group 1;" ::: "memory")

// ---------------------------------------------------------------------------
// Projection GEMM body (R7 version). C[m,n] = A[m,:]·W[n,:] + bias[n].
// Tile 128x128, 2-stage cp.async, tf32 cvt on fragments (hidden under MMA).
// mode 0: out[m][n] fp32; mode 1: out[b,h,s,d] tf32; mode 2: tf32 * 1/8 (Q)
// ---------------------------------------------------------------------------
__device__ __forceinline__ void proj_body(const float* __restrict__ A,
                                          const float* __restrict__ W,
                                          const float* __restrict__ bias,
                                          float* __restrict__ out, int mode,
                                          float (*sA)[128][36], float (*sB)[128][36]) {
    const int tid = threadIdx.x, lane = tid & 31, w = tid >> 5;
    const int wm = (w >> 2) * 64, wn = (w & 3) * 32;
    const int m0 = blockIdx.y * 128, n0 = blockIdx.x * 128;

    float acc[4][4][4] = {};

    #pragma unroll
    for (int i = tid; i < 1024; i += 256) {
        int r = i >> 3, c4 = (i & 7) * 4;
        CP_ASYNC16(smaddr(&sA[0][r][c4]), &A[(size_t)(m0 + r) * H_ + c4]);
        CP_ASYNC16(smaddr(&sB[0][r][c4]), &W[(size_t)(n0 + r) * H_ + c4]);
    }
    CP_COMMIT();

    for (int it = 0; it < 32; it++) {
        const int s = it & 1;
        if (it + 1 < 32) {
            const int kn = (it + 1) * 32, sn = s ^ 1;
            #pragma unroll
            for (int i = tid; i < 1024; i += 256) {
                int r = i >> 3, c4 = (i & 7) * 4;
                CP_ASYNC16(smaddr(&sA[sn][r][c4]), &A[(size_t)(m0 + r) * H_ + kn + c4]);
                CP_ASYNC16(smaddr(&sB[sn][r][c4]), &W[(size_t)(n0 + r) * H_ + kn + c4]);
            }
            CP_COMMIT();
            CP_WAIT1();
        } else {
            CP_WAIT0();
        }
        __syncthreads();

        #pragma unroll
        for (int ks = 0; ks < 4; ks++) {
            uint32_t af[4][4], bf[4][2];
            #pragma unroll
            for (int mt = 0; mt < 4; mt++) {
                lda_frag(af[mt], &sA[s][0][0], 36, wm + mt * 16, ks * 8, lane);
                #pragma unroll
                for (int j = 0; j < 4; j++) af[mt][j] = f2tf32(__uint_as_float(af[mt][j]));
            }
            #pragma unroll
            for (int nt = 0; nt < 4; nt++) {
                ldb_frag(bf[nt], &sB[s][0][0], 36, wn + nt * 8, ks * 8, lane);
                bf[nt][0] = f2tf32(__uint_as_float(bf[nt][0]));
                bf[nt][1] = f2tf32(__uint_as_float(bf[nt][1]));
            }
            #pragma unroll
            for (int mt = 0; mt < 4; mt++)
                #pragma unroll
                for (int nt = 0; nt < 4; nt++)
                    mma_tf32(acc[mt][nt], af[mt], bf[nt]);
        }
        __syncthreads();
    }

    #pragma unroll
    for (int mt = 0; mt < 4; mt++) {
        #pragma unroll
        for (int nt = 0; nt < 4; nt++) {
            int r0 = m0 + wm + mt * 16 + (lane >> 2);
            int c0 = n0 + wn + nt * 8 + (lane & 3) * 2;
            #pragma unroll
            for (int e = 0; e < 4; e++) {
                int m = r0 + (e >> 1) * 8;
                int n = c0 + (e & 1);
                float v = acc[mt][nt][e] + bias[n];
                if (mode == 0) {
                    out[(size_t)m * H_ + n] = v;
                } else {
                    int b = m >> 11, sq = m & 2047, h = n >> 6, dd = n & 63;
                    float o = tf32f(v);
                    if (mode == 2) o *= SCALE_INV;   // exact (exponent shift)
                    out[(((size_t)(b * NH_ + h) * S_) + sq) * HD_ + dd] = o;
                }
            }
        }
    }
}

__global__ __launch_bounds__(256, 2) void proj_mma(const float* __restrict__ A,
                                                   const float* __restrict__ W,
                                                   const float* __restrict__ bias,
                                                   float* __restrict__ out, int mode) {
    __shared__ float sA[2][128][36];
    __shared__ float sB[2][128][36];
    proj_body(A, W, bias, out, mode, sA, sB);
}

// Fused Q+K projection: blockIdx.z selects operand set (one launch, one tail).
__global__ __launch_bounds__(256, 2) void proj_qk(const float* __restrict__ q,
                                                  const float* __restrict__ kk,
                                                  const float* __restrict__ Wq,
                                                  const float* __restrict__ Wk,
                                                  const float* __restrict__ bq,
                                                  const float* __restrict__ bk,
                                                  float* __restrict__ oq,
                                                  float* __restrict__ ok) {
    __shared__ float sA[2][128][36];
    __shared__ float sB[2][128][36];
    if (blockIdx.z == 0)
        proj_body(q, Wq, bq, oq, 2, sA, sB);     // Q: tf32 * 1/8
    else
        proj_body(kk, Wk, bk, ok, 1, sA, sB);    // K: tf32
}

// ---------------------------------------------------------------------------
// Energy + exp + mask (R7 version — best measured). Tile 128(q) x 64(k).
// Q pre-scaled by 1/8. Mask prefetched + bit-packed. Writes tf32 unnorm P.
// ---------------------------------------------------------------------------
__global__ __launch_bounds__(256, 3) void energy_exp(const int* __restrict__ mask,
                                                     float* __restrict__ attn,
                                                     float* __restrict__ psum) {
    __shared__ union {
        struct { float A[128][68]; float B[64][68]; } ld;
        float E[128][68];
    } sm;
    const int tid = threadIdx.x, lane = tid & 31, w = tid >> 5;
    const int wm = (w >> 1) * 32, wn = (w & 1) * 32;
    const int bh = blockIdx.z, b = bh >> 4;
    const int q0 = blockIdx.y * 128, k0 = blockIdx.x * 64;
    const int kblk = blockIdx.x;
    const float* Qb = g_Q + (size_t)bh * S_ * HD_;
    const float* Kb = g_K + (size_t)bh * S_ * HD_;

    #pragma unroll
    for (int i = tid; i < 2048; i += 256) {
        int r = i >> 4, c4 = (i & 15) * 4;
        CP_ASYNC16(smaddr(&sm.ld.A[r][c4]), &Qb[(size_t)(q0 + r) * HD_ + c4]);
    }
    #pragma unroll
    for (int i = tid; i < 1024; i += 256) {
        int r = i >> 4, c4 = (i & 15) * 4;
        CP_ASYNC16(smaddr(&sm.ld.B[r][c4]), &Kb[(size_t)(k0 + r) * HD_ + c4]);
    }
    CP_COMMIT();

    const int* mb = mask + (size_t)b * S_ * S_;
    const int cl = (tid & 15) * 4;
    const int k = k0 + cl;
    uint32_t pmask = 0;
    #pragma unroll
    for (int j = 0; j < 8; j++) {
        int q = q0 + j * 16 + (tid >> 4);
        int4 mv = *(const int4*)&mb[(size_t)q * S_ + k];
        uint32_t bits = (mv.x ? 1u : 0u) | (mv.y ? 2u : 0u)
                      | (mv.z ? 4u : 0u) | (mv.w ? 8u : 0u);
        pmask |= bits << (4 * j);
    }

    CP_WAIT0();
    __syncthreads();

    float acc[2][4][4] = {};
    #pragma unroll
    for (int ks = 0; ks < 8; ks++) {
        uint32_t af[2][4], bf[4][2];
        #pragma unroll
        for (int mt = 0; mt < 2; mt++) lda_frag(af[mt], &sm.ld.A[0][0], 68, wm + mt * 16, ks * 8, lane);
        #pragma unroll
        for (int nt = 0; nt < 4; nt++) ldb_frag(bf[nt], &sm.ld.B[0][0], 68, wn + nt * 8, ks * 8, lane);
        #pragma unroll
        for (int mt = 0; mt < 2; mt++)
            #pragma unroll
            for (int nt = 0; nt < 4; nt++)
                mma_tf32(acc[mt][nt], af[mt], bf[nt]);
    }
    __syncthreads();   // all warps done reading Q/K before E overwrites

    #pragma unroll
    for (int mt = 0; mt < 2; mt++) {
        int r = wm + mt * 16 + (lane >> 2);
        #pragma unroll
        for (int nt = 0; nt < 4; nt++) {
            int lc = wn + nt * 8 + (lane & 3) * 2;
            sm.E[r][lc]         = acc[mt][nt][0];
            sm.E[r][lc + 1]     = acc[mt][nt][1];
            sm.E[r + 8][lc]     = acc[mt][nt][2];
            sm.E[r + 8][lc + 1] = acc[mt][nt][3];
        }
    }
    __syncthreads();

    float* ab = attn + (size_t)bh * S_ * S_;
    #pragma unroll
    for (int j = 0; j < 8; j++) {
        int row = j * 16 + (tid >> 4);
        int q = q0 + row;
        float4 ev = *(float4*)&sm.E[row][cl];
        uint32_t bits = (pmask >> (4 * j)) & 0xfu;
        float p0 = (bits & 1u) ? tf32f(__expf(ev.x)) : 0.f;
        float p1 = (bits & 2u) ? tf32f(__expf(ev.y)) : 0.f;
        float p2 = (bits & 4u) ? tf32f(__expf(ev.z)) : 0.f;
        float p3 = (bits & 8u) ? tf32f(__expf(ev.w)) : 0.f;
        float4 pv4 = { p0, p1, p2, p3 };
        *(float4*)&ab[(size_t)q * S_ + k] = pv4;
        float v = (p0 + p1) + (p2 + p3);
        v += __shfl_xor_sync(0xffffffffu, v, 1);
        v += __shfl_xor_sync(0xffffffffu, v, 2);
        v += __shfl_xor_sync(0xffffffffu, v, 4);
        v += __shfl_xor_sync(0xffffffffu, v, 8);
        if ((tid & 15) == 0)
            psum[((size_t)bh * S_ + q) * 32 + kblk] = v;
    }
}

// ---------------------------------------------------------------------------
// PV + normalize (R7 version). Tile 128(q) x 64(d), K chunked by 32,
// 2-stage cp.async. MMA on unnormalized tf32 P; normalization at stores.
// ---------------------------------------------------------------------------
__global__ __launch_bounds__(256, 3) void pv_norm(float* __restrict__ attn,
                                                  const float* __restrict__ psum) {
    __shared__ float sP[2][128][36];
    __shared__ float sV[2][32][68];
    __shared__ float sInv[128];
    const int tid = threadIdx.x, lane = tid & 31, w = tid >> 5;
    const int wm = (w >> 1) * 32, wn = (w & 1) * 32;
    const int bh = blockIdx.y, b = bh >> 4, h = bh & 15;
    const int q0 = blockIdx.x * 128;
    float* Pb = attn + (size_t)bh * S_ * S_;
    const float* Vb = g_V + (size_t)bh * S_ * HD_;

    if (tid < 128) {
        const float* ps = psum + ((size_t)bh * S_ + q0 + tid) * 32;
        float sum = 0.f;
        #pragma unroll
        for (int i = 0; i < 32; i++) sum += ps[i];
        sInv[tid] = 1.0f / sum;
    }

    #pragma unroll
    for (int i = tid; i < 1024; i += 256) {
        int r = i >> 3, c4 = (i & 7) * 4;
        CP_ASYNC16(smaddr(&sP[0][r][c4]), &Pb[(size_t)(q0 + r) * S_ + c4]);
    }
    #pragma unroll
    for (int i = tid; i < 512; i += 256) {
        int r = i >> 4, c4 = (i & 15) * 4;
        CP_ASYNC16(smaddr(&sV[0][r][c4]), &Vb[(size_t)r * HD_ + c4]);
    }
    CP_COMMIT();

    float acc[2][4][4] = {};

    for (int it = 0; it < 64; it++) {
        const int kc = it * 32, s = it & 1;
        if (it + 1 < 64) {
            const int kn = kc + 32, sn = s ^ 1;
            #pragma unroll
            for (int i = tid; i < 1024; i += 256) {
                int r = i >> 3, c4 = (i & 7) * 4;
                CP_ASYNC16(smaddr(&sP[sn][r][c4]), &Pb[(size_t)(q0 + r) * S_ + kn + c4]);
            }
            #pragma unroll
            for (int i = tid; i < 512; i += 256) {
                int r = i >> 4, c4 = (i & 15) * 4;
                CP_ASYNC16(smaddr(&sV[sn][r][c4]), &Vb[(size_t)(kn + r) * HD_ + c4]);
            }
            CP_COMMIT();
            CP_WAIT1();
        } else {
            CP_WAIT0();
        }
        __syncthreads();

        #pragma unroll
        for (int ks = 0; ks < 4; ks++) {
            uint32_t af[2][4], bf[4][2];
            #pragma unroll
            for (int mt = 0; mt < 2; mt++) lda_frag(af[mt], &sP[s][0][0], 36, wm + mt * 16, ks * 8, lane);
            #pragma unroll
            for (int nt = 0; nt < 4; nt++) {
                const float* p = &sV[s][ks * 8 + (lane & 3)][wn + nt * 8 + (lane >> 2)];
                bf[nt][0] = __float_as_uint(p[0]);
                bf[nt][1] = __float_as_uint(p[4 * 68]);
            }
            #pragma unroll
            for (int mt = 0; mt < 2; mt++)
                #pragma unroll
                for (int nt = 0; nt < 4; nt++)
                    mma_tf32(acc[mt][nt], af[mt], bf[nt]);
        }

        #pragma unroll
        for (int i = tid; i < 1024; i += 256) {
            int r = i >> 3, c4 = (i & 7) * 4;
            float inv = sInv[r];
            float4 v = *(float4*)&sP[s][r][c4];
            v.x *= inv; v.y *= inv; v.z *= inv; v.w *= inv;
            *(float4*)&Pb[(size_t)(q0 + r) * S_ + kc + c4] = v;
        }
        __syncthreads();
    }

    #pragma unroll
    for (int mt = 0; mt < 2; mt++) {
        #pragma unroll
        for (int nt = 0; nt < 4; nt++) {
            int rr = wm + mt * 16 + (lane >> 2);
            int c0 = wn + nt * 8 + (lane & 3) * 2;
            #pragma unroll
            for (int e = 0; e < 4; e++) {
                int rl = rr + (e >> 1) * 8;
                int q = q0 + rl;
                int d = c0 + (e & 1);
                g_X[((size_t)(b * S_ + q)) * H_ + h * HD_ + d] = acc[mt][nt][e] * sInv[rl];
            }
        }
    }
}

// ---------------------------------------------------------------------------
extern "C" void kernel_launch(void* const* d_in, const int* in_sizes, int n_in,
                              void* d_out, int out_size) {
    const float* query = (const float*)d_in[0];
    const float* key   = (const float*)d_in[1];
    const float* value = (const float*)d_in[2];
    const int*   mask  = (const int*)d_in[3];
    const float* Wq = (const float*)d_in[4];  const float* bq = (const float*)d_in[5];
    const float* Wk = (const float*)d_in[6];  const float* bk = (const float*)d_in[7];
    const float* Wv = (const float*)d_in[8];  const float* bv = (const float*)d_in[9];
    const float* Wo = (const float*)d_in[10]; const float* bo = (const float*)d_in[11];

    float* out  = (float*)d_out;
    float* attn = out + (size_t)B_ * S_ * H_;

    float *gQ, *gK, *gV, *gX, *gPS;
    cudaGetSymbolAddress((void**)&gQ, g_Q);
    cudaGetSymbolAddress((void**)&gK, g_K);
    cudaGetSymbolAddress((void**)&gV, g_V);
    cudaGetSymbolAddress((void**)&gX, g_X);
    cudaGetSymbolAddress((void**)&gPS, g_psum);

    // Side stream for the V projection (independent of energy) — standard
    // capture fork/join via events. Created fresh per call (host objects
    // only; no device allocation).
    cudaStream_t s1;
    cudaEvent_t e0, e1;
    cudaStreamCreateWithFlags(&s1, cudaStreamNonBlocking);
    cudaEventCreateWithFlags(&e0, cudaEventDisableTiming);
    cudaEventCreateWithFlags(&e1, cudaEventDisableTiming);

    dim3 grid_proj(H_ / 128, M_ / 128);        // (8, 64)

    // Fork: V projection runs concurrently with QK projections + energy.
    cudaEventRecord(e0, 0);
    cudaStreamWaitEvent(s1, e0, 0);
    proj_mma<<<grid_proj, 256, 0, s1>>>(value, Wv, bv, gV, 1);
    cudaEventRecord(e1, s1);

    // Main stream: fused Q+K projection (one launch, one tail).
    dim3 grid_qk(H_ / 128, M_ / 128, 2);       // (8, 64, 2)
    proj_qk<<<grid_qk, 256>>>(query, key, Wq, Wk, bq, bk, gQ, gK);

    dim3 grid_e(S_ / 64, S_ / 128, B_ * NH_);  // (32, 16, 64)
    energy_exp<<<grid_e, 256>>>(mask, attn, gPS);

    // Join: pv needs g_V.
    cudaStreamWaitEvent(0, e1, 0);

    dim3 grid_pv(S_ / 128, B_ * NH_);          // (16, 64)
    pv_norm<<<grid_pv, 256>>>(attn, gPS);

    proj_mma<<<grid_proj, 256>>>(gX, Wo, bo, out, 0);
}

// round 16
// speedup vs baseline: 1.1494x; 1.0195x over previous
#include <cuda_runtime.h>
#include <cuda_fp16.h>
#include <math.h>
#include <stdint.h>

#define B_  4
#define S_  2048
#define H_  1024
#define NH_ 16
#define HD_ 64
#define M_  (B_ * S_)
#define SCALE_INV 0.125f

// Scratch (device globals — no allocation allowed)
__device__ float g_Q[M_ * H_];            // [B,NH,S,HD]  tf32-rounded, pre-scaled by 1/8
__device__ float g_K[M_ * H_];            // [B,NH,S,HD]  tf32-rounded
__device__ float g_V[M_ * H_];            // [B,NH,S,HD]  tf32-rounded
__device__ float g_X[M_ * H_];            // [B,S,H]
__device__ float g_psum[64 * S_ * 32];    // [bh][q][kblock(64)] partial row sums
__device__ __half g_Ph[(size_t)64 * S_ * S_];  // unnormalized P, fp16 (512 MB)

// ---------------------------------------------------------------------------
__device__ __forceinline__ uint32_t f2tf32(float x) {  // round-to-nearest tf32
    uint32_t r; asm("cvt.rna.tf32.f32 %0, %1;" : "=r"(r) : "f"(x)); return r;
}
__device__ __forceinline__ float tf32f(float x) { return __uint_as_float(f2tf32(x)); }

__device__ __forceinline__ void mma_tf32(float* c, const uint32_t* a, const uint32_t* b) {
    asm volatile("mma.sync.aligned.m16n8k8.row.col.f32.tf32.tf32.f32 "
        "{%0,%1,%2,%3}, {%4,%5,%6,%7}, {%8,%9}, {%0,%1,%2,%3};"
        : "+f"(c[0]), "+f"(c[1]), "+f"(c[2]), "+f"(c[3])
        : "r"(a[0]), "r"(a[1]), "r"(a[2]), "r"(a[3]), "r"(b[0]), "r"(b[1]));
}

__device__ __forceinline__ void lda_frag(uint32_t* a, const float* s, int lds,
                                         int mbase, int k, int lane) {
    const float* p = s + (size_t)(mbase + (lane >> 2)) * lds + k + (lane & 3);
    a[0] = __float_as_uint(p[0]);
    a[1] = __float_as_uint(p[8 * lds]);
    a[2] = __float_as_uint(p[4]);
    a[3] = __float_as_uint(p[8 * lds + 4]);
}
__device__ __forceinline__ void ldb_frag(uint32_t* b, const float* s, int lds,
                                         int nbase, int k, int lane) {
    const float* p = s + (size_t)(nbase + (lane >> 2)) * lds + k + (lane & 3);
    b[0] = __float_as_uint(p[0]);
    b[1] = __float_as_uint(p[4]);
}

__device__ __forceinline__ uint32_t smaddr(const void* p) {
    return (uint32_t)__cvta_generic_to_shared(p);
}
#define CP_ASYNC16(dst, src) \
    asm volatile("cp.async.cg.shared.global [%0], [%1], 16;" :: "r"(dst), "l"(src))
#define CP_COMMIT() asm volatile("cp.async.commit_group;" ::: "memory")
#define CP_WAIT0()  asm volatile("cp.async.wait_group 0;" ::: "memory")
#define CP_WAIT1()  asm volatile("cp.async.wait_group 1;" ::: "memory")

// ---------------------------------------------------------------------------
// Projection GEMM body (R7 version, best measured).
// mode 0: out[m][n] fp32; mode 1: out[b,h,s,d] tf32; mode 2: tf32 * 1/8 (Q)
// ---------------------------------------------------------------------------
__device__ __forceinline__ void proj_body(const float* __restrict__ A,
                                          const float* __restrict__ W,
                                          const float* __restrict__ bias,
                                          float* __restrict__ out, int mode,
                                          float (*sA)[128][36], float (*sB)[128][36]) {
    const int tid = threadIdx.x, lane = tid & 31, w = tid >> 5;
    const int wm = (w >> 2) * 64, wn = (w & 3) * 32;
    const int m0 = blockIdx.y * 128, n0 = blockIdx.x * 128;

    float acc[4][4][4] = {};

    #pragma unroll
    for (int i = tid; i < 1024; i += 256) {
        int r = i >> 3, c4 = (i & 7) * 4;
        CP_ASYNC16(smaddr(&sA[0][r][c4]), &A[(size_t)(m0 + r) * H_ + c4]);
        CP_ASYNC16(smaddr(&sB[0][r][c4]), &W[(size_t)(n0 + r) * H_ + c4]);
    }
    CP_COMMIT();

    for (int it = 0; it < 32; it++) {
        const int s = it & 1;
        if (it + 1 < 32) {
            const int kn = (it + 1) * 32, sn = s ^ 1;
            #pragma unroll
            for (int i = tid; i < 1024; i += 256) {
                int r = i >> 3, c4 = (i & 7) * 4;
                CP_ASYNC16(smaddr(&sA[sn][r][c4]), &A[(size_t)(m0 + r) * H_ + kn + c4]);
                CP_ASYNC16(smaddr(&sB[sn][r][c4]), &W[(size_t)(n0 + r) * H_ + kn + c4]);
            }
            CP_COMMIT();
            CP_WAIT1();
        } else {
            CP_WAIT0();
        }
        __syncthreads();

        #pragma unroll
        for (int ks = 0; ks < 4; ks++) {
            uint32_t af[4][4], bf[4][2];
            #pragma unroll
            for (int mt = 0; mt < 4; mt++) {
                lda_frag(af[mt], &sA[s][0][0], 36, wm + mt * 16, ks * 8, lane);
                #pragma unroll
                for (int j = 0; j < 4; j++) af[mt][j] = f2tf32(__uint_as_float(af[mt][j]));
            }
            #pragma unroll
            for (int nt = 0; nt < 4; nt++) {
                ldb_frag(bf[nt], &sB[s][0][0], 36, wn + nt * 8, ks * 8, lane);
                bf[nt][0] = f2tf32(__uint_as_float(bf[nt][0]));
                bf[nt][1] = f2tf32(__uint_as_float(bf[nt][1]));
            }
            #pragma unroll
            for (int mt = 0; mt < 4; mt++)
                #pragma unroll
                for (int nt = 0; nt < 4; nt++)
                    mma_tf32(acc[mt][nt], af[mt], bf[nt]);
        }
        __syncthreads();
    }

    #pragma unroll
    for (int mt = 0; mt < 4; mt++) {
        #pragma unroll
        for (int nt = 0; nt < 4; nt++) {
            int r0 = m0 + wm + mt * 16 + (lane >> 2);
            int c0 = n0 + wn + nt * 8 + (lane & 3) * 2;
            #pragma unroll
            for (int e = 0; e < 4; e++) {
                int m = r0 + (e >> 1) * 8;
                int n = c0 + (e & 1);
                float v = acc[mt][nt][e] + bias[n];
                if (mode == 0) {
                    out[(size_t)m * H_ + n] = v;
                } else {
                    int b = m >> 11, sq = m & 2047, h = n >> 6, dd = n & 63;
                    float o = tf32f(v);
                    if (mode == 2) o *= SCALE_INV;   // exact (exponent shift)
                    out[(((size_t)(b * NH_ + h) * S_) + sq) * HD_ + dd] = o;
                }
            }
        }
    }
}

__global__ __launch_bounds__(256, 2) void proj_mma(const float* __restrict__ A,
                                                   const float* __restrict__ W,
                                                   const float* __restrict__ bias,
                                                   float* __restrict__ out, int mode) {
    __shared__ float sA[2][128][36];
    __shared__ float sB[2][128][36];
    proj_body(A, W, bias, out, mode, sA, sB);
}

// Fused Q+K projection: blockIdx.z selects operand set (one launch, one tail).
__global__ __launch_bounds__(256, 2) void proj_qk(const float* __restrict__ q,
                                                  const float* __restrict__ kk,
                                                  const float* __restrict__ Wq,
                                                  const float* __restrict__ Wk,
                                                  const float* __restrict__ bq,
                                                  const float* __restrict__ bk,
                                                  float* __restrict__ oq,
                                                  float* __restrict__ ok) {
    __shared__ float sA[2][128][36];
    __shared__ float sB[2][128][36];
    if (blockIdx.z == 0)
        proj_body(q, Wq, bq, oq, 2, sA, sB);     // Q: tf32 * 1/8
    else
        proj_body(kk, Wk, bk, ok, 1, sA, sB);    // K: tf32
}

// ---------------------------------------------------------------------------
// Energy + exp + mask. Tile 128(q) x 64(k). Q pre-scaled by 1/8. Mask
// prefetched + bit-packed. Writes fp16 unnormalized P to g_Ph (half bytes).
// ---------------------------------------------------------------------------
__global__ __launch_bounds__(256, 3) void energy_exp(const int* __restrict__ mask,
                                                     __half* __restrict__ ph,
                                                     float* __restrict__ psum) {
    __shared__ union {
        struct { float A[128][68]; float B[64][68]; } ld;
        float E[128][68];
    } sm;
    const int tid = threadIdx.x, lane = tid & 31, w = tid >> 5;
    const int wm = (w >> 1) * 32, wn = (w & 1) * 32;
    const int bh = blockIdx.z, b = bh >> 4;
    const int q0 = blockIdx.y * 128, k0 = blockIdx.x * 64;
    const int kblk = blockIdx.x;
    const float* Qb = g_Q + (size_t)bh * S_ * HD_;
    const float* Kb = g_K + (size_t)bh * S_ * HD_;

    #pragma unroll
    for (int i = tid; i < 2048; i += 256) {
        int r = i >> 4, c4 = (i & 15) * 4;
        CP_ASYNC16(smaddr(&sm.ld.A[r][c4]), &Qb[(size_t)(q0 + r) * HD_ + c4]);
    }
    #pragma unroll
    for (int i = tid; i < 1024; i += 256) {
        int r = i >> 4, c4 = (i & 15) * 4;
        CP_ASYNC16(smaddr(&sm.ld.B[r][c4]), &Kb[(size_t)(k0 + r) * HD_ + c4]);
    }
    CP_COMMIT();

    const int* mb = mask + (size_t)b * S_ * S_;
    const int cl = (tid & 15) * 4;
    const int k = k0 + cl;
    uint32_t pmask = 0;
    #pragma unroll
    for (int j = 0; j < 8; j++) {
        int q = q0 + j * 16 + (tid >> 4);
        int4 mv = *(const int4*)&mb[(size_t)q * S_ + k];
        uint32_t bits = (mv.x ? 1u : 0u) | (mv.y ? 2u : 0u)
                      | (mv.z ? 4u : 0u) | (mv.w ? 8u : 0u);
        pmask |= bits << (4 * j);
    }

    CP_WAIT0();
    __syncthreads();

    float acc[2][4][4] = {};
    #pragma unroll
    for (int ks = 0; ks < 8; ks++) {
        uint32_t af[2][4], bf[4][2];
        #pragma unroll
        for (int mt = 0; mt < 2; mt++) lda_frag(af[mt], &sm.ld.A[0][0], 68, wm + mt * 16, ks * 8, lane);
        #pragma unroll
        for (int nt = 0; nt < 4; nt++) ldb_frag(bf[nt], &sm.ld.B[0][0], 68, wn + nt * 8, ks * 8, lane);
        #pragma unroll
        for (int mt = 0; mt < 2; mt++)
            #pragma unroll
            for (int nt = 0; nt < 4; nt++)
                mma_tf32(acc[mt][nt], af[mt], bf[nt]);
    }
    __syncthreads();   // all warps done reading Q/K before E overwrites

    #pragma unroll
    for (int mt = 0; mt < 2; mt++) {
        int r = wm + mt * 16 + (lane >> 2);
        #pragma unroll
        for (int nt = 0; nt < 4; nt++) {
            int lc = wn + nt * 8 + (lane & 3) * 2;
            sm.E[r][lc]         = acc[mt][nt][0];
            sm.E[r][lc + 1]     = acc[mt][nt][1];
            sm.E[r + 8][lc]     = acc[mt][nt][2];
            sm.E[r + 8][lc + 1] = acc[mt][nt][3];
        }
    }
    __syncthreads();

    __half* pb = ph + (size_t)bh * S_ * S_;
    #pragma unroll
    for (int j = 0; j < 8; j++) {
        int row = j * 16 + (tid >> 4);
        int q = q0 + row;
        float4 ev = *(float4*)&sm.E[row][cl];
        uint32_t bits = (pmask >> (4 * j)) & 0xfu;
        __half h0 = (bits & 1u) ? __float2half_rn(__expf(ev.x)) : __half(0.f);
        __half h1 = (bits & 2u) ? __float2half_rn(__expf(ev.y)) : __half(0.f);
        __half h2 = (bits & 4u) ? __float2half_rn(__expf(ev.z)) : __half(0.f);
        __half h3 = (bits & 8u) ? __float2half_rn(__expf(ev.w)) : __half(0.f);
        __half2 h01 = __halves2half2(h0, h1);
        __half2 h23 = __halves2half2(h2, h3);
        uint2 pk = { *(uint32_t*)&h01, *(uint32_t*)&h23 };
        *(uint2*)&pb[(size_t)q * S_ + k] = pk;     // 8B coalesced
        float v = (__half2float(h0) + __half2float(h1))
                + (__half2float(h2) + __half2float(h3));
        v += __shfl_xor_sync(0xffffffffu, v, 1);
        v += __shfl_xor_sync(0xffffffffu, v, 2);
        v += __shfl_xor_sync(0xffffffffu, v, 4);
        v += __shfl_xor_sync(0xffffffffu, v, 8);
        if ((tid & 15) == 0)
            psum[((size_t)bh * S_ + q) * 32 + kblk] = v;
    }
}

// ---------------------------------------------------------------------------
// PV + normalize. Tile 128(q) x 64(d). P read as fp16 (register-prefetched
// LDG, cvt->fp32 at STS — exact; values already tf32-representable). V via
// cp.async. Writes normalized fp32 attn from staged tile; X normalized.
// ---------------------------------------------------------------------------
__global__ __launch_bounds__(256, 3) void pv_norm(const __half* __restrict__ ph,
                                                  float* __restrict__ attn,
                                                  const float* __restrict__ psum) {
    __shared__ float sP[2][128][36];
    __shared__ float sV[2][32][68];
    __shared__ float sInv[128];
    const int tid = threadIdx.x, lane = tid & 31, w = tid >> 5;
    const int wm = (w >> 1) * 32, wn = (w & 1) * 32;
    const int bh = blockIdx.y, b = bh >> 4, h = bh & 15;
    const int q0 = blockIdx.x * 128;
    const __half* Phb = ph + (size_t)bh * S_ * S_;
    float* Ab = attn + (size_t)bh * S_ * S_;
    const float* Vb = g_V + (size_t)bh * S_ * HD_;

    if (tid < 128) {
        const float* ps = psum + ((size_t)bh * S_ + q0 + tid) * 32;
        float sum = 0.f;
        #pragma unroll
        for (int i = 0; i < 32; i++) sum += ps[i];
        sInv[tid] = 1.0f / sum;
    }

    // Per-thread P staging coords: 2 threads per row, 16 halves each.
    const int pr = tid >> 1;              // row 0..127
    const int pc = (tid & 1) * 16;        // half-col offset 0 or 16
    const __half* prow = &Phb[(size_t)(q0 + pr) * S_ + pc];

    // Prefetch P chunk 0 (registers) + V chunk 0 (cp.async).
    uint4 pA = *(const uint4*)(prow);         // halves pc..pc+7
    uint4 pB = *(const uint4*)(prow + 8);     // halves pc+8..pc+15
    #pragma unroll
    for (int i = tid; i < 512; i += 256) {
        int r = i >> 4, c4 = (i & 15) * 4;
        CP_ASYNC16(smaddr(&sV[0][r][c4]), &Vb[(size_t)r * HD_ + c4]);
    }
    CP_COMMIT();

    float acc[2][4][4] = {};

    for (int it = 0; it < 64; it++) {
        const int kc = it * 32, s = it & 1;

        // cvt + STS P chunk it from prefetched registers.
        {
            float* dst = &sP[s][pr][pc];
            const __half2* ha = (const __half2*)&pA;
            const __half2* hb = (const __half2*)&pB;
            float2 f0 = __half22float2(ha[0]), f1 = __half22float2(ha[1]);
            float2 f2 = __half22float2(ha[2]), f3 = __half22float2(ha[3]);
            float4 v0 = { f0.x, f0.y, f1.x, f1.y };
            float4 v1 = { f2.x, f2.y, f3.x, f3.y };
            *(float4*)(dst)     = v0;
            *(float4*)(dst + 4) = v1;
            f0 = __half22float2(hb[0]); f1 = __half22float2(hb[1]);
            f2 = __half22float2(hb[2]); f3 = __half22float2(hb[3]);
            float4 v2 = { f0.x, f0.y, f1.x, f1.y };
            float4 v3 = { f2.x, f2.y, f3.x, f3.y };
            *(float4*)(dst + 8)  = v2;
            *(float4*)(dst + 12) = v3;
        }

        if (it + 1 < 64) {
            const int kn = kc + 32, sn = s ^ 1;
            pA = *(const uint4*)(prow + kn);
            pB = *(const uint4*)(prow + kn + 8);
            #pragma unroll
            for (int i = tid; i < 512; i += 256) {
                int r = i >> 4, c4 = (i & 15) * 4;
                CP_ASYNC16(smaddr(&sV[sn][r][c4]), &Vb[(size_t)(kn + r) * HD_ + c4]);
            }
            CP_COMMIT();
            CP_WAIT1();
        } else {
            CP_WAIT0();
        }
        __syncthreads();

        #pragma unroll
        for (int ks = 0; ks < 4; ks++) {
            uint32_t af[2][4], bf[4][2];
            #pragma unroll
            for (int mt = 0; mt < 2; mt++) lda_frag(af[mt], &sP[s][0][0], 36, wm + mt * 16, ks * 8, lane);
            #pragma unroll
            for (int nt = 0; nt < 4; nt++) {
                const float* p = &sV[s][ks * 8 + (lane & 3)][wn + nt * 8 + (lane >> 2)];
                bf[nt][0] = __float_as_uint(p[0]);
                bf[nt][1] = __float_as_uint(p[4 * 68]);
            }
            #pragma unroll
            for (int mt = 0; mt < 2; mt++)
                #pragma unroll
                for (int nt = 0; nt < 4; nt++)
                    mma_tf32(acc[mt][nt], af[mt], bf[nt]);
        }

        // Normalized attention store (fp32) from the staged tile.
        #pragma unroll
        for (int i = tid; i < 1024; i += 256) {
            int r = i >> 3, c4 = (i & 7) * 4;
            float inv = sInv[r];
            float4 v = *(float4*)&sP[s][r][c4];
            v.x *= inv; v.y *= inv; v.z *= inv; v.w *= inv;
            *(float4*)&Ab[(size_t)(q0 + r) * S_ + kc + c4] = v;
        }
        __syncthreads();
    }

    #pragma unroll
    for (int mt = 0; mt < 2; mt++) {
        #pragma unroll
        for (int nt = 0; nt < 4; nt++) {
            int rr = wm + mt * 16 + (lane >> 2);
            int c0 = wn + nt * 8 + (lane & 3) * 2;
            #pragma unroll
            for (int e = 0; e < 4; e++) {
                int rl = rr + (e >> 1) * 8;
                int q = q0 + rl;
                int d = c0 + (e & 1);
                g_X[((size_t)(b * S_ + q)) * H_ + h * HD_ + d] = acc[mt][nt][e] * sInv[rl];
            }
        }
    }
}

// ---------------------------------------------------------------------------
extern "C" void kernel_launch(void* const* d_in, const int* in_sizes, int n_in,
                              void* d_out, int out_size) {
    const float* query = (const float*)d_in[0];
    const float* key   = (const float*)d_in[1];
    const float* value = (const float*)d_in[2];
    const int*   mask  = (const int*)d_in[3];
    const float* Wq = (const float*)d_in[4];  const float* bq = (const float*)d_in[5];
    const float* Wk = (const float*)d_in[6];  const float* bk = (const float*)d_in[7];
    const float* Wv = (const float*)d_in[8];  const float* bv = (const float*)d_in[9];
    const float* Wo = (const float*)d_in[10]; const float* bo = (const float*)d_in[11];

    float* out  = (float*)d_out;
    float* attn = out + (size_t)B_ * S_ * H_;

    float *gQ, *gK, *gV, *gX, *gPS;
    __half* gPh;
    cudaGetSymbolAddress((void**)&gQ, g_Q);
    cudaGetSymbolAddress((void**)&gK, g_K);
    cudaGetSymbolAddress((void**)&gV, g_V);
    cudaGetSymbolAddress((void**)&gX, g_X);
    cudaGetSymbolAddress((void**)&gPS, g_psum);
    cudaGetSymbolAddress((void**)&gPh, g_Ph);

    // Side stream for the V projection (independent of energy).
    cudaStream_t s1;
    cudaEvent_t e0, e1;
    cudaStreamCreateWithFlags(&s1, cudaStreamNonBlocking);
    cudaEventCreateWithFlags(&e0, cudaEventDisableTiming);
    cudaEventCreateWithFlags(&e1, cudaEventDisableTiming);

    dim3 grid_proj(H_ / 128, M_ / 128);        // (8, 64)

    // Fork: V projection runs concurrently with QK projections + energy.
    cudaEventRecord(e0, 0);
    cudaStreamWaitEvent(s1, e0, 0);
    proj_mma<<<grid_proj, 256, 0, s1>>>(value, Wv, bv, gV, 1);
    cudaEventRecord(e1, s1);

    // Main stream: fused Q+K projection (one launch, one tail).
    dim3 grid_qk(H_ / 128, M_ / 128, 2);       // (8, 64, 2)
    proj_qk<<<grid_qk, 256>>>(query, key, Wq, Wk, bq, bk, gQ, gK);

    dim3 grid_e(S_ / 64, S_ / 128, B_ * NH_);  // (32, 16, 64)
    energy_exp<<<grid_e, 256>>>(mask, gPh, gPS);

    // Join: pv needs g_V.
    cudaStreamWaitEvent(0, e1, 0);

    dim3 grid_pv(S_ / 128, B_ * NH_);          // (16, 64)
    pv_norm<<<grid_pv, 256>>>(gPh, attn, gPS);

    proj_mma<<<grid_proj, 256>>>(gX, Wo, bo, out, 0);
}